// round 1
// baseline (speedup 1.0000x reference)
#include <cuda_runtime.h>
#include <math.h>

#define I_ 16
#define T_ 64
#define Q_ 196
#define K_ 32
#define E_ 512
#define H_ 8
#define D_ 64

#define OUT_N   (I_*T_*E_)                 // 524288
#define ATT_N   (I_*T_*H_*Q_*K_)           // 51380224
#define SCALE_  0.044194173824159216f      // 1/sqrt(512)
#define LOG2E_  1.4426950408889634f

// -------- scratch (device globals: no allocations allowed) --------
__device__ float g_query[I_*H_*Q_*D_];   // (i,h,q,d)
__device__ float g_key  [T_*H_*K_*D_];   // (t,h,k,d)
__device__ float g_value[T_*H_*K_*D_];   // (t,h,k,d)
__device__ float g_pooled[I_*T_*E_];     // (i*T+t, e)
__device__ float g_maskf[T_*K_];

// -------- packed fp32x2 FMA (Blackwell) --------
__device__ __forceinline__ void ffma2(float& cx, float& cy,
                                      float ax, float ay,
                                      float bx, float by) {
    asm("{\n\t"
        ".reg .b64 ra, rb, rc;\n\t"
        "mov.b64 ra, {%2, %3};\n\t"
        "mov.b64 rb, {%4, %5};\n\t"
        "mov.b64 rc, {%0, %1};\n\t"
        "fma.rn.f32x2 rc, ra, rb, rc;\n\t"
        "mov.b64 {%0, %1}, rc;\n\t"
        "}"
        : "+f"(cx), "+f"(cy)
        : "f"(ax), "f"(ay), "f"(bx), "f"(by));
}

// -------- mask conversion (robust to bool/int32/float32 serialization) --------
__global__ void mask_kernel(const void* mp) {
    __shared__ int mode;  // 0=bytes(bool/int8), 1=int32, 2=float32
    if (threadIdx.x == 0) {
        const unsigned char* b = (const unsigned char*)mp;
        int c3f = 0, cnz = 0;
        // Only inspect first 2048 bytes: always in-bounds for every candidate layout.
        for (int k = 0; k < 512; k++) {
            if (b[4*k+3] == 0x3F) c3f++;                  // float32 1.0f high byte
            if (b[4*k+1] | b[4*k+2]) cnz++;               // nonzero mid bytes => 1-byte layout
        }
        mode = (c3f > 8) ? 2 : ((cnz > 8) ? 0 : 1);
    }
    __syncthreads();
    int m = mode;
    for (int idx = threadIdx.x; idx < T_*K_; idx += blockDim.x) {
        float v;
        if (m == 0)      v = ((const unsigned char*)mp)[idx] ? 1.f : 0.f;
        else if (m == 1) v = ((const int*)mp)[idx] ? 1.f : 0.f;
        else             v = (((const float*)mp)[idx] != 0.f) ? 1.f : 0.f;
        g_maskf[idx] = v;
    }
}

// -------- per-head linear projection: Y[(o,h),l,e] = sum_d X[o,l,h*64+d] * W[e,d] --------
__global__ void proj_kernel(const float* __restrict__ X, const float* __restrict__ W,
                            int which, int L, int rowsPerBlk) {
    __shared__ float sWt[64*64];    // W transposed: sWt[d*64+e] = W[e*64+d]
    __shared__ float sX[98*64];
    float* Y = (which == 0) ? g_query : ((which == 1) ? g_key : g_value);

    int o = blockIdx.x / H_, h = blockIdx.x % H_;
    int r0 = blockIdx.y * rowsPerBlk;
    int nr = min(rowsPerBlk, L - r0);
    int tid = threadIdx.x;

    for (int idx = tid; idx < 4096; idx += 256) {
        int e = idx >> 6, d = idx & 63;
        sWt[d*64 + e] = W[idx];
    }
    for (int idx = tid; idx < nr*64; idx += 256) {
        int l = idx >> 6, d = idx & 63;
        sX[idx] = X[(o*L + r0 + l)*E_ + h*64 + d];
    }
    __syncthreads();

    int e = tid & 63;
    for (int l = tid >> 6; l < nr; l += 4) {
        float acc = 0.f;
        #pragma unroll
        for (int d = 0; d < 64; d++) acc += sX[l*64 + d] * sWt[d*64 + e];
        Y[((o*H_ + h)*L + r0 + l)*64 + e] = acc;
    }
}

// -------- fused energy + dual softmax + pooled-AV, one CTA per (i,t,h) tile --------
__global__ void __launch_bounds__(256, 2)
attn_kernel(float* __restrict__ out, int wAttn, int wText) {
    extern __shared__ float sm[];
    float* sQ    = sm;                 // 196*64 = 12544
    float* sE    = sQ    + Q_*D_;      // 196*32 =  6272
    float* sV    = sE    + Q_*K_;      //  32*64 =  2048
    float* sRinv = sV    + K_*D_;      //           196
    float* sMk   = sRinv + Q_;         //            32
    float* sPE   = sMk   + K_;         //           256
    float* sPA   = sPE   + 256;        //           256
    float* sCA   = sPA   + 256;        //            32
    float* sCT   = sCA   + 32;         //            32

    int bid = blockIdx.x;
    int h = bid & 7, t = (bid >> 3) & 63;
    int i = bid >> 9;
    int tid = threadIdx.x, lane = tid & 31, warp = tid >> 5;

    // stage Q and V tiles, mask row
    {
        const float4* src = (const float4*)(g_query + (i*H_ + h)*(Q_*D_));
        float4* dst = (float4*)sQ;
        for (int idx = tid; idx < (Q_*D_)/4; idx += 256) dst[idx] = src[idx];
        const float4* vs = (const float4*)(g_value + (t*H_ + h)*(K_*D_));
        float4* vd = (float4*)sV;
        for (int idx = tid; idx < (K_*D_)/4; idx += 256) vd[idx] = vs[idx];
        if (tid < K_) sMk[tid] = g_maskf[t*K_ + tid];
    }
    // K row (k = lane) resident in registers as 32 float2
    float2 k2[32];
    {
        const float2* kp = (const float2*)(g_key + (t*H_ + h)*(K_*D_) + lane*D_);
        #pragma unroll
        for (int j = 0; j < 32; j++) k2[j] = kp[j];
    }
    __syncthreads();

    float mreg = sMk[lane];
    long long tileOff = (long long)bid * (Q_*K_);
    float* attnOut = out + OUT_N + tileOff;
    float* textOut = out + OUT_N + (long long)ATT_N + tileOff;

    // energy + exp + row softmax (over k)
    for (int q = warp; q < Q_; q += 8) {
        const float4* qp = (const float4*)(sQ + q*D_);
        float ax = 0.f, ay = 0.f;
        #pragma unroll
        for (int j = 0; j < 16; j++) {
            float4 v = qp[j];
            ffma2(ax, ay, v.x, v.y, k2[2*j].x,   k2[2*j].y);
            ffma2(ax, ay, v.z, v.w, k2[2*j+1].x, k2[2*j+1].y);
        }
        float s = (ax + ay) * SCALE_;
        // no max-subtraction needed: |s| is small; masked -> exactly 0
        float e = (mreg != 0.f) ? exp2f(s * LOG2E_) : 0.f;
        float rs = e;
        #pragma unroll
        for (int o = 16; o > 0; o >>= 1) rs += __shfl_xor_sync(0xffffffffu, rs, o);
        float rinv = 1.f / rs;
        if (wAttn) attnOut[q*K_ + lane] = e * rinv;
        sE[q*K_ + lane] = e;
        if (lane == 0) sRinv[q] = rinv;
    }
    __syncthreads();

    // column sums: colE (for text softmax), colA (= column sum of attention, for pooling)
    {
        float pe = 0.f, pa = 0.f;
        for (int q = warp; q < Q_; q += 8) {
            float e = sE[q*K_ + lane];
            pe += e;
            pa += e * sRinv[q];
        }
        sPE[warp*32 + lane] = pe;
        sPA[warp*32 + lane] = pa;
    }
    __syncthreads();
    if (tid < 32) {
        float ce = 0.f, ca = 0.f;
        #pragma unroll
        for (int w = 0; w < 8; w++) { ce += sPE[w*32 + tid]; ca += sPA[w*32 + tid]; }
        sCA[tid] = ca;
        sCT[tid] = (ce > 0.f) ? (1.f / ce) : 0.f;
    }
    __syncthreads();

    // text attention (softmax over q); fully-masked columns -> uniform 1/Q
    if (wText) {
        float ct = sCT[lane];
        bool cm = (mreg == 0.f);
        for (int q = warp; q < Q_; q += 8) {
            float v = cm ? (1.f / (float)Q_) : sE[q*K_ + lane] * ct;
            textOut[q*K_ + lane] = v;
        }
    }

    // pooled[i,t,h*64+d] = (1/Q) * sum_k colA[k] * V[k,d]
    if (tid < 64) {
        float a = 0.f;
        #pragma unroll
        for (int k = 0; k < 32; k++) a += sCA[k] * sV[k*D_ + tid];
        g_pooled[(long long)(bid >> 3)*E_ + h*64 + tid] = a * (1.f / (float)Q_);
    }
}

// -------- final: out[row,f] = sum_e pooled[row,e]*Wo[f,e] + bo[f], rows = I*T --------
__global__ void fc_kernel(const float* __restrict__ Wo, const float* __restrict__ bo,
                          float* __restrict__ out) {
    __shared__ float sA[64*33];
    __shared__ float sB[64*33];
    int rt = blockIdx.x * 64;   // row tile   (16 tiles)
    int ct = blockIdx.y * 64;   // f-col tile (8 tiles)
    int tid = threadIdx.x;
    int tx = tid & 15, ty = tid >> 4;
    float acc[4][4] = {};

    for (int kc = 0; kc < E_; kc += 32) {
        for (int idx = tid; idx < 2048; idx += 256) {
            int r = idx >> 5, kk = idx & 31;
            sA[r*33 + kk] = g_pooled[(rt + r)*E_ + kc + kk];
            sB[r*33 + kk] = Wo[(ct + r)*E_ + kc + kk];
        }
        __syncthreads();
        #pragma unroll
        for (int kk = 0; kk < 32; kk++) {
            float a[4], b[4];
            #pragma unroll
            for (int r = 0; r < 4; r++) a[r] = sA[(ty*4 + r)*33 + kk];
            #pragma unroll
            for (int c = 0; c < 4; c++) b[c] = sB[(tx*4 + c)*33 + kk];
            #pragma unroll
            for (int r = 0; r < 4; r++)
                #pragma unroll
                for (int c = 0; c < 4; c++) acc[r][c] += a[r] * b[c];
        }
        __syncthreads();
    }
    #pragma unroll
    for (int r = 0; r < 4; r++)
        #pragma unroll
        for (int c = 0; c < 4; c++)
            out[(rt + ty*4 + r)*E_ + ct + tx*4 + c] = acc[r][c] + bo[ct + tx*4 + c];
}

// -------- launch --------
extern "C" void kernel_launch(void* const* d_in, const int* in_sizes, int n_in,
                              void* d_out, int out_size) {
    const float* image = (const float*)d_in[0];
    const float* text  = (const float*)d_in[1];
    const void*  mask  =                d_in[2];
    const float* Wq    = (const float*)d_in[3];
    const float* Wk    = (const float*)d_in[4];
    const float* Wv    = (const float*)d_in[5];
    const float* Wo    = (const float*)d_in[6];
    const float* bo    = (const float*)d_in[7];
    float* out = (float*)d_out;

    const int SMEM_BYTES = (Q_*D_ + Q_*K_ + K_*D_ + Q_ + K_ + 256 + 256 + 32 + 32) * 4;
    cudaFuncSetAttribute(attn_kernel, cudaFuncAttributeMaxDynamicSharedMemorySize, SMEM_BYTES);

    mask_kernel<<<1, 256>>>(mask);
    proj_kernel<<<dim3(I_*H_, 2), 256>>>(image, Wq, 0, Q_, 98);
    proj_kernel<<<dim3(T_*H_, 1), 256>>>(text,  Wk, 1, K_, 32);
    proj_kernel<<<dim3(T_*H_, 1), 256>>>(text,  Wv, 2, K_, 32);

    int wAttn = out_size >= (OUT_N + ATT_N);
    int wText = out_size >= (OUT_N + 2*ATT_N);
    attn_kernel<<<I_*T_*H_, 256, SMEM_BYTES>>>(out, wAttn, wText);

    if (out_size >= OUT_N)
        fc_kernel<<<dim3(16, 8), 256>>>(Wo, bo, out);
}

// round 2
// speedup vs baseline: 1.2711x; 1.2711x over previous
#include <cuda_runtime.h>
#include <math.h>

#define I_ 16
#define T_ 64
#define Q_ 196
#define K_ 32
#define E_ 512
#define H_ 8
#define D_ 64
#define TT_ 4                               // t-values per CTA

#define OUT_N   (I_*T_*E_)                  // 524288
#define ATT_N   (I_*T_*H_*Q_*K_)            // 51380224
#define SCALE_  0.044194173824159216f       // 1/sqrt(512)
#define LOG2E_  1.4426950408889634f

typedef unsigned long long ull;

// -------- scratch (device globals: no allocations allowed) --------
__device__ float g_query[I_*H_*Q_*D_];   // (i,h,q,d)
__device__ float g_key  [T_*H_*K_*D_];   // (t,h,k,d)
__device__ float g_value[T_*H_*K_*D_];   // (t,h,k,d)
__device__ float g_pooled[I_*T_*E_];     // (i*T+t, e)
__device__ float g_maskf[T_*K_];

// -------- packed fp32x2 FMA, zero pack/unpack overhead --------
__device__ __forceinline__ ull fma2(ull a, ull b, ull c) {
    ull d;
    asm("fma.rn.f32x2 %0, %1, %2, %3;" : "=l"(d) : "l"(a), "l"(b), "l"(c));
    return d;
}
__device__ __forceinline__ float2 unpack2(ull a) {
    float2 r;
    asm("mov.b64 {%0, %1}, %2;" : "=f"(r.x), "=f"(r.y) : "l"(a));
    return r;
}

// -------- mask conversion (robust to bool/int32/float32 serialization) --------
__global__ void mask_kernel(const void* mp) {
    __shared__ int mode;  // 0=bytes, 1=int32, 2=float32
    if (threadIdx.x == 0) {
        const unsigned char* b = (const unsigned char*)mp;
        int c3f = 0, cnz = 0;
        for (int k = 0; k < 512; k++) {          // first 2048 bytes only (in-bounds for all layouts)
            if (b[4*k+3] == 0x3F) c3f++;
            if (b[4*k+1] | b[4*k+2]) cnz++;
        }
        mode = (c3f > 8) ? 2 : ((cnz > 8) ? 0 : 1);
    }
    __syncthreads();
    int m = mode;
    for (int idx = threadIdx.x; idx < T_*K_; idx += blockDim.x) {
        float v;
        if (m == 0)      v = ((const unsigned char*)mp)[idx] ? 1.f : 0.f;
        else if (m == 1) v = ((const int*)mp)[idx] ? 1.f : 0.f;
        else             v = (((const float*)mp)[idx] != 0.f) ? 1.f : 0.f;
        g_maskf[idx] = v;
    }
}

// -------- register-tiled per-head projection (fc-style 4x4 microtile) --------
// Y[row_out(r), e] = sum_d X[r*512 + h*64 + d] * W[e*64 + d]
__global__ void proj2_kernel(const float* __restrict__ X, const float* __restrict__ W,
                             float* __restrict__ Y, int which) {
    __shared__ float sA[64*33];
    __shared__ float sB[64*33];
    int h = blockIdx.y;
    int r0 = blockIdx.x * 64;
    int tid = threadIdx.x;
    int tx = tid & 15, ty = tid >> 4;
    float acc[4][4] = {};

    #pragma unroll
    for (int kc = 0; kc < 64; kc += 32) {
        for (int idx = tid; idx < 2048; idx += 256) {
            int r = idx >> 5, kk = idx & 31;
            sA[r*33 + kk] = X[(r0 + r)*E_ + h*64 + kc + kk];
            sB[r*33 + kk] = W[r*64 + kc + kk];
        }
        __syncthreads();
        #pragma unroll
        for (int kk = 0; kk < 32; kk++) {
            float a[4], b[4];
            #pragma unroll
            for (int r = 0; r < 4; r++) a[r] = sA[(ty*4 + r)*33 + kk];
            #pragma unroll
            for (int c = 0; c < 4; c++) b[c] = sB[(tx*4 + c)*33 + kk];
            #pragma unroll
            for (int r = 0; r < 4; r++)
                #pragma unroll
                for (int c = 0; c < 4; c++) acc[r][c] += a[r] * b[c];
        }
        __syncthreads();
    }
    #pragma unroll
    for (int r = 0; r < 4; r++) {
        int row = r0 + ty*4 + r;
        long long obase;
        if (which == 0) { int i = row / Q_, q = row % Q_;  obase = ((long long)(i*H_ + h)*Q_ + q)*64; }
        else            { int t = row >> 5, k = row & 31;  obase = ((long long)(t*H_ + h)*K_ + k)*64; }
        #pragma unroll
        for (int c = 0; c < 4; c++)
            Y[obase + tx*4 + c] = acc[r][c];
    }
}

// -------- fused energy + dual softmax + pooled-AV --------
// grid: (I*H, T/TT); block 256. One CTA: fixed (i,h), TT consecutive t.
__global__ void __launch_bounds__(256, 2)
attn_kernel(float* __restrict__ out, int wAttn, int wText) {
    extern __shared__ float sm[];
    float* sQ    = sm;                  // 196*64 = 12544
    float* sE    = sQ    + Q_*D_;       // 196*32 =  6272
    float* sV    = sE    + Q_*K_;       //  32*64 =  2048
    float* sRinv = sV    + K_*D_;       //           196
    float* sMk   = sRinv + Q_ + 4;      //            32  (pad keeps 16B alignment)
    float* sPE   = sMk   + K_;          //           256
    float* sPA   = sPE   + 256;         //           256
    float* sCA   = sPA   + 256;         //            32
    float* sTA   = sCA   + 32;          //            32
    float* sTB   = sTA   + 32;          //            32

    int ih = blockIdx.x;                // i*8 + h
    int h = ih & 7, i = ih >> 3;
    int t0 = blockIdx.y * TT_;
    int tid = threadIdx.x, lane = tid & 31, warp = tid >> 5;

    // stage Q tile once
    {
        const float4* src = (const float4*)(g_query + (long long)ih*(Q_*D_));
        float4* dst = (float4*)sQ;
        for (int idx = tid; idx < (Q_*D_)/4; idx += 256) dst[idx] = src[idx];
    }

    unsigned sQaddr = (unsigned)__cvta_generic_to_shared(sQ);

    for (int tt = 0; tt < TT_; tt++) {
        int t = t0 + tt;
        __syncthreads();   // previous iteration's readers done; Q staged (first iter)

        // stage V tile + mask row
        {
            const float4* vs = (const float4*)(g_value + (long long)(t*H_ + h)*(K_*D_));
            float4* vd = (float4*)sV;
            for (int idx = tid; idx < (K_*D_)/4; idx += 256) vd[idx] = vs[idx];
            if (tid < K_) sMk[tid] = g_maskf[t*K_ + tid];
        }
        // K row (k = lane) into packed u64 registers
        ull kk[32];
        {
            const ulonglong2* kp = (const ulonglong2*)(g_key + (long long)(t*H_ + h)*(K_*D_) + lane*D_);
            #pragma unroll
            for (int m = 0; m < 16; m++) { ulonglong2 v = kp[m]; kk[2*m] = v.x; kk[2*m+1] = v.y; }
        }
        __syncthreads();

        float mreg = sMk[lane];

        // energy + exp + row-softmax denominators
        for (int q = warp; q < Q_; q += 8) {
            unsigned qa = sQaddr + q*256;
            ull a0 = 0ULL, a1 = 0ULL;
            #pragma unroll
            for (int j = 0; j < 16; j++) {
                ull q0, q1;
                asm volatile("ld.shared.v2.b64 {%0,%1}, [%2];"
                             : "=l"(q0), "=l"(q1) : "r"(qa + j*16));
                a0 = fma2(q0, kk[2*j],   a0);
                a1 = fma2(q1, kk[2*j+1], a1);
            }
            float2 f0 = unpack2(a0), f1 = unpack2(a1);
            float s = ((f0.x + f0.y) + (f1.x + f1.y)) * SCALE_;
            float e = (mreg != 0.f) ? exp2f(s * LOG2E_) : 0.f;
            float rs = e;
            #pragma unroll
            for (int o = 16; o > 0; o >>= 1) rs += __shfl_xor_sync(0xffffffffu, rs, o);
            sE[q*K_ + lane] = e;
            if (lane == 0) sRinv[q] = 1.f / rs;
        }
        __syncthreads();

        // column partials: colE (text softmax) and colA (pooling)
        {
            float pe = 0.f, pa = 0.f;
            for (int q = warp; q < Q_; q += 8) {
                float e = sE[q*K_ + lane];
                pe += e;
                pa += e * sRinv[q];
            }
            sPE[warp*32 + lane] = pe;
            sPA[warp*32 + lane] = pa;
        }
        __syncthreads();
        if (tid < 32) {
            float ce = 0.f, ca = 0.f;
            #pragma unroll
            for (int w = 0; w < 8; w++) { ce += sPE[w*32 + tid]; ca += sPA[w*32 + tid]; }
            sCA[tid] = ca;
            float m = sMk[tid];
            sTA[tid] = (m != 0.f) ? (1.f / ce) : 0.f;     // e==0 on masked cols -> e*tA = 0
            sTB[tid] = (m != 0.f) ? 0.f : (1.f / (float)Q_);
        }
        __syncthreads();

        // vectorized writeout: attention + text_attention (STG.128 only)
        long long tileOff = (((long long)(i*T_ + t)*H_ + h)) * (Q_*K_);
        if (wAttn | wText) {
            float4* attn4 = (float4*)(out + OUT_N + tileOff);
            float4* text4 = (float4*)(out + OUT_N + (long long)ATT_N + tileOff);
            const float4* sE4 = (const float4*)sE;
            const float4* tA4 = (const float4*)sTA;
            const float4* tB4 = (const float4*)sTB;
            for (int idx = tid; idx < Q_*8; idx += 256) {
                int q = idx >> 3, c = idx & 7;
                float4 e4 = sE4[idx];
                if (wAttn) {
                    float rinv = sRinv[q];
                    float4 a4 = { e4.x*rinv, e4.y*rinv, e4.z*rinv, e4.w*rinv };
                    attn4[idx] = a4;
                }
                if (wText) {
                    float4 ta = tA4[c], tb = tB4[c];
                    float4 x4 = { fmaf(e4.x, ta.x, tb.x), fmaf(e4.y, ta.y, tb.y),
                                  fmaf(e4.z, ta.z, tb.z), fmaf(e4.w, ta.w, tb.w) };
                    text4[idx] = x4;
                }
            }
        }

        // pooled[i*T+t, h*64+d] = (1/Q) * sum_k colA[k] * V[k,d]
        if (tid < 64) {
            float a = 0.f;
            #pragma unroll
            for (int k = 0; k < 32; k++) a += sCA[k] * sV[k*D_ + tid];
            g_pooled[(long long)(i*T_ + t)*E_ + h*64 + tid] = a * (1.f / (float)Q_);
        }
    }
}

// -------- final: out[row,f] = sum_e pooled[row,e]*Wo[f,e] + bo[f] --------
__global__ void fc_kernel(const float* __restrict__ Wo, const float* __restrict__ bo,
                          float* __restrict__ out) {
    __shared__ float sA[64*33];
    __shared__ float sB[64*33];
    int rt = blockIdx.x * 64;
    int ct = blockIdx.y * 64;
    int tid = threadIdx.x;
    int tx = tid & 15, ty = tid >> 4;
    float acc[4][4] = {};

    for (int kc = 0; kc < E_; kc += 32) {
        for (int idx = tid; idx < 2048; idx += 256) {
            int r = idx >> 5, kk = idx & 31;
            sA[r*33 + kk] = g_pooled[(rt + r)*E_ + kc + kk];
            sB[r*33 + kk] = Wo[(ct + r)*E_ + kc + kk];
        }
        __syncthreads();
        #pragma unroll
        for (int kk = 0; kk < 32; kk++) {
            float a[4], b[4];
            #pragma unroll
            for (int r = 0; r < 4; r++) a[r] = sA[(ty*4 + r)*33 + kk];
            #pragma unroll
            for (int c = 0; c < 4; c++) b[c] = sB[(tx*4 + c)*33 + kk];
            #pragma unroll
            for (int r = 0; r < 4; r++)
                #pragma unroll
                for (int c = 0; c < 4; c++) acc[r][c] += a[r] * b[c];
        }
        __syncthreads();
    }
    #pragma unroll
    for (int r = 0; r < 4; r++)
        #pragma unroll
        for (int c = 0; c < 4; c++)
            out[(rt + ty*4 + r)*E_ + ct + tx*4 + c] = acc[r][c] + bo[ct + tx*4 + c];
}

// -------- launch --------
extern "C" void kernel_launch(void* const* d_in, const int* in_sizes, int n_in,
                              void* d_out, int out_size) {
    const float* image = (const float*)d_in[0];
    const float* text  = (const float*)d_in[1];
    const void*  mask  =                d_in[2];
    const float* Wq    = (const float*)d_in[3];
    const float* Wk    = (const float*)d_in[4];
    const float* Wv    = (const float*)d_in[5];
    const float* Wo    = (const float*)d_in[6];
    const float* bo    = (const float*)d_in[7];
    float* out = (float*)d_out;

    const int SMEM_BYTES = (Q_*D_ + Q_*K_ + K_*D_ + Q_ + 4 + K_ + 256 + 256 + 32 + 32 + 32) * 4;
    cudaFuncSetAttribute(attn_kernel, cudaFuncAttributeMaxDynamicSharedMemorySize, SMEM_BYTES);

    mask_kernel<<<1, 256>>>(mask);

    float* d_q; cudaGetSymbolAddress((void**)&d_q, g_query);
    float* d_k; cudaGetSymbolAddress((void**)&d_k, g_key);
    float* d_v; cudaGetSymbolAddress((void**)&d_v, g_value);
    proj2_kernel<<<dim3((I_*Q_)/64, H_), 256>>>(image, Wq, d_q, 0);
    proj2_kernel<<<dim3((T_*K_)/64, H_), 256>>>(text,  Wk, d_k, 1);
    proj2_kernel<<<dim3((T_*K_)/64, H_), 256>>>(text,  Wv, d_v, 2);

    int wAttn = out_size >= (OUT_N + ATT_N);
    int wText = out_size >= (OUT_N + 2*ATT_N);
    attn_kernel<<<dim3(I_*H_, T_/TT_), 256, SMEM_BYTES>>>(out, wAttn, wText);

    if (out_size >= OUT_N)
        fc_kernel<<<dim3(16, 8), 256>>>(Wo, bo, out);
}

// round 3
// speedup vs baseline: 1.6971x; 1.3352x over previous
#include <cuda_runtime.h>
#include <math.h>

#define I_ 16
#define T_ 64
#define Q_ 196
#define K_ 32
#define E_ 512
#define H_ 8
#define D_ 64
#define TT_ 4                               // t-values per CTA

#define OUT_N   (I_*T_*E_)                  // 524288
#define ATT_N   (I_*T_*H_*Q_*K_)            // 51380224
#define SCALE_  0.044194173824159216f       // 1/sqrt(512)
#define LOG2E_  1.4426950408889634f
#define EST_    36                          // sE row stride (floats)

typedef unsigned long long ull;

// -------- scratch (device globals: no allocations allowed) --------
__device__ float g_query[I_*H_*Q_*D_];   // (i,h,q,d)
__device__ float g_key  [T_*H_*K_*D_];   // (t,h,k,d)
__device__ float g_value[T_*H_*K_*D_];   // (t,h,k,d)
__device__ float g_pooled[I_*T_*E_];     // (i*T+t, e)
__device__ float g_maskf[T_*K_];

// -------- packed fp32x2 FMA --------
__device__ __forceinline__ ull fma2(ull a, ull b, ull c) {
    ull d;
    asm("fma.rn.f32x2 %0, %1, %2, %3;" : "=l"(d) : "l"(a), "l"(b), "l"(c));
    return d;
}
__device__ __forceinline__ float2 unpack2(ull a) {
    float2 r;
    asm("mov.b64 {%0, %1}, %2;" : "=f"(r.x), "=f"(r.y) : "l"(a));
    return r;
}

// -------- mask conversion (robust to bool/int32/float32 serialization) --------
__global__ void mask_kernel(const void* mp) {
    __shared__ int mode;
    if (threadIdx.x == 0) {
        const unsigned char* b = (const unsigned char*)mp;
        int c3f = 0, cnz = 0;
        for (int k = 0; k < 512; k++) {
            if (b[4*k+3] == 0x3F) c3f++;
            if (b[4*k+1] | b[4*k+2]) cnz++;
        }
        mode = (c3f > 8) ? 2 : ((cnz > 8) ? 0 : 1);
    }
    __syncthreads();
    int m = mode;
    for (int idx = threadIdx.x; idx < T_*K_; idx += blockDim.x) {
        float v;
        if (m == 0)      v = ((const unsigned char*)mp)[idx] ? 1.f : 0.f;
        else if (m == 1) v = ((const int*)mp)[idx] ? 1.f : 0.f;
        else             v = (((const float*)mp)[idx] != 0.f) ? 1.f : 0.f;
        g_maskf[idx] = v;
    }
}

// -------- register-tiled per-head projection --------
__global__ void proj2_kernel(const float* __restrict__ X, const float* __restrict__ W,
                             float* __restrict__ Y, int which) {
    __shared__ float sA[64*33];
    __shared__ float sB[64*33];
    int h = blockIdx.y;
    int r0 = blockIdx.x * 64;
    int tid = threadIdx.x;
    int tx = tid & 15, ty = tid >> 4;
    float acc[4][4] = {};

    #pragma unroll
    for (int kc = 0; kc < 64; kc += 32) {
        for (int idx = tid; idx < 2048; idx += 256) {
            int r = idx >> 5, kk = idx & 31;
            sA[r*33 + kk] = X[(r0 + r)*E_ + h*64 + kc + kk];
            sB[r*33 + kk] = W[r*64 + kc + kk];
        }
        __syncthreads();
        #pragma unroll
        for (int kk = 0; kk < 32; kk++) {
            float a[4], b[4];
            #pragma unroll
            for (int r = 0; r < 4; r++) a[r] = sA[(ty*4 + r)*33 + kk];
            #pragma unroll
            for (int c = 0; c < 4; c++) b[c] = sB[(tx*4 + c)*33 + kk];
            #pragma unroll
            for (int r = 0; r < 4; r++)
                #pragma unroll
                for (int c = 0; c < 4; c++) acc[r][c] += a[r] * b[c];
        }
        __syncthreads();
    }
    #pragma unroll
    for (int r = 0; r < 4; r++) {
        int row = r0 + ty*4 + r;
        long long obase;
        if (which == 0) { int i = row / Q_, q = row % Q_;  obase = ((long long)(i*H_ + h)*Q_ + q)*64; }
        else            { int t = row >> 5, k = row & 31;  obase = ((long long)(t*H_ + h)*K_ + k)*64; }
        #pragma unroll
        for (int c = 0; c < 4; c++)
            Y[obase + tx*4 + c] = acc[r][c];
    }
}

// -------- fused energy + dual softmax + pooled-AV, lane-owns-q layout --------
// grid: (I*H, T/TT); block 256. Thread tid owns q-row tid (196 active).
__global__ void __launch_bounds__(256, 2)
attn_kernel(float* __restrict__ out, int wAttn, int wText) {
    extern __shared__ float sm[];
    float* sE    = sm;                  // 196*36 = 7056 (also Q staging: 98*68=6664)
    float* sK    = sE    + Q_*EST_;     // 2048
    float* sV    = sK    + K_*D_;       // 2048
    float* sRinv = sV    + K_*D_;       // 196 (+4 pad)
    float* sMk   = sRinv + Q_ + 4;      // 32
    float* sPE   = sMk   + K_;          // 256
    float* sPA   = sPE   + 256;         // 256
    float* sCA   = sPA   + 256;         // 32
    float* sTA   = sCA   + 32;          // 32
    float* sTB   = sTA   + 32;          // 32

    int ih = blockIdx.x;                // i*8 + h
    int h = ih & 7, i = ih >> 3;
    int t0 = blockIdx.y * TT_;
    int tid = threadIdx.x, lane = tid & 31, warp = tid >> 5;

    unsigned sEaddr = (unsigned)__cvta_generic_to_shared(sE);
    unsigned sKaddr = (unsigned)__cvta_generic_to_shared(sK);

    // ---- load own Q row into packed registers (staged via smem, 2 chunks) ----
    ull qreg[32];
    {
        const float* Qg = g_query + (long long)ih*(Q_*D_);
        #pragma unroll
        for (int chunk = 0; chunk < 2; chunk++) {
            int r0 = chunk*98;
            for (int idx = tid; idx < 98*16; idx += 256) {
                int r = idx >> 4, c = idx & 15;
                *(float4*)&sE[r*68 + c*4] = *(const float4*)&Qg[(r0 + r)*64 + c*4];
            }
            __syncthreads();
            if (tid >= r0 && tid < r0 + 98) {
                unsigned a = sEaddr + (unsigned)(tid - r0)*(68*4);
                #pragma unroll
                for (int j = 0; j < 16; j++)
                    asm volatile("ld.shared.v2.b64 {%0,%1}, [%2];"
                                 : "=l"(qreg[2*j]), "=l"(qreg[2*j+1]) : "r"(a + j*16));
            }
            __syncthreads();
        }
    }

    for (int tt = 0; tt < TT_; tt++) {
        int t = t0 + tt;

        // stage K, V tiles + mask row (coalesced float4)
        {
            const float4* ks = (const float4*)(g_key   + (long long)(t*H_ + h)*(K_*D_));
            const float4* vs = (const float4*)(g_value + (long long)(t*H_ + h)*(K_*D_));
            float4* kd = (float4*)sK;
            float4* vd = (float4*)sV;
            for (int idx = tid; idx < (K_*D_)/4; idx += 256) { kd[idx] = ks[idx]; vd[idx] = vs[idx]; }
            if (tid < K_) sMk[tid] = g_maskf[t*K_ + tid];
        }
        __syncthreads();

        // ---- energy + exp + row sum: all register-private, K via broadcast LDS ----
        if (tid < Q_) {
            float rowsum = 0.f;
            #pragma unroll 4
            for (int k = 0; k < K_; k++) {
                unsigned kb = sKaddr + k*256;
                ull a0 = 0ULL, a1 = 0ULL;
                #pragma unroll
                for (int j = 0; j < 16; j++) {
                    ull k0, k1;
                    asm volatile("ld.shared.v2.b64 {%0,%1}, [%2];"
                                 : "=l"(k0), "=l"(k1) : "r"(kb + j*16));
                    a0 = fma2(qreg[2*j],   k0, a0);
                    a1 = fma2(qreg[2*j+1], k1, a1);
                }
                float2 f0 = unpack2(a0), f1 = unpack2(a1);
                float s = ((f0.x + f0.y) + (f1.x + f1.y)) * SCALE_;
                float e = (sMk[k] != 0.f) ? exp2f(s * LOG2E_) : 0.f;
                rowsum += e;
                sE[tid*EST_ + k] = e;
            }
            sRinv[tid] = 1.f / rowsum;
        }
        __syncthreads();

        // ---- column partials over q: colE (text softmax) and colA (pooling) ----
        {
            float pe = 0.f, pa = 0.f;
            for (int q = warp; q < Q_; q += 8) {
                float e = sE[q*EST_ + lane];
                pe += e;
                pa += e * sRinv[q];
            }
            sPE[warp*32 + lane] = pe;
            sPA[warp*32 + lane] = pa;
        }
        __syncthreads();
        if (tid < 32) {
            float ce = 0.f, ca = 0.f;
            #pragma unroll
            for (int w = 0; w < 8; w++) { ce += sPE[w*32 + tid]; ca += sPA[w*32 + tid]; }
            sCA[tid] = ca;
            float m = sMk[tid];
            sTA[tid] = (m != 0.f) ? (1.f / ce) : 0.f;
            sTB[tid] = (m != 0.f) ? 0.f : (1.f / (float)Q_);
        }
        __syncthreads();

        // ---- vectorized writeout: attention + text_attention (STG.128 only) ----
        long long tileOff = (((long long)(i*T_ + t)*H_ + h)) * (Q_*K_);
        if (wAttn | wText) {
            float4* attn4 = (float4*)(out + OUT_N + tileOff);
            float4* text4 = (float4*)(out + OUT_N + (long long)ATT_N + tileOff);
            const float4* sE4 = (const float4*)sE;
            const float4* tA4 = (const float4*)sTA;
            const float4* tB4 = (const float4*)sTB;
            for (int idx = tid; idx < Q_*8; idx += 256) {
                int q = idx >> 3, c = idx & 7;
                float4 e4 = sE4[q*(EST_/4) + c];
                if (wAttn) {
                    float rinv = sRinv[q];
                    float4 a4 = { e4.x*rinv, e4.y*rinv, e4.z*rinv, e4.w*rinv };
                    attn4[idx] = a4;
                }
                if (wText) {
                    float4 ta = tA4[c], tb = tB4[c];
                    float4 x4 = { fmaf(e4.x, ta.x, tb.x), fmaf(e4.y, ta.y, tb.y),
                                  fmaf(e4.z, ta.z, tb.z), fmaf(e4.w, ta.w, tb.w) };
                    text4[idx] = x4;
                }
            }
        }

        // ---- pooled[i*T+t, h*64+d] = (1/Q) * sum_k colA[k] * V[k,d] ----
        if (tid < 64) {
            float a = 0.f;
            #pragma unroll
            for (int k = 0; k < 32; k++) a += sCA[k] * sV[k*D_ + tid];
            g_pooled[(long long)(i*T_ + t)*E_ + h*64 + tid] = a * (1.f / (float)Q_);
        }
        __syncthreads();   // protect sE/sK/sV before next tile overwrites
    }
}

// -------- final: out[row,f] = sum_e pooled[row,e]*Wo[f,e] + bo[f] --------
__global__ void fc_kernel(const float* __restrict__ Wo, const float* __restrict__ bo,
                          float* __restrict__ out) {
    __shared__ float sA[64*33];
    __shared__ float sB[64*33];
    int rt = blockIdx.x * 64;
    int ct = blockIdx.y * 64;
    int tid = threadIdx.x;
    int tx = tid & 15, ty = tid >> 4;
    float acc[4][4] = {};

    for (int kc = 0; kc < E_; kc += 32) {
        for (int idx = tid; idx < 2048; idx += 256) {
            int r = idx >> 5, kk = idx & 31;
            sA[r*33 + kk] = g_pooled[(rt + r)*E_ + kc + kk];
            sB[r*33 + kk] = Wo[(ct + r)*E_ + kc + kk];
        }
        __syncthreads();
        #pragma unroll
        for (int kk = 0; kk < 32; kk++) {
            float a[4], b[4];
            #pragma unroll
            for (int r = 0; r < 4; r++) a[r] = sA[(ty*4 + r)*33 + kk];
            #pragma unroll
            for (int c = 0; c < 4; c++) b[c] = sB[(tx*4 + c)*33 + kk];
            #pragma unroll
            for (int r = 0; r < 4; r++)
                #pragma unroll
                for (int c = 0; c < 4; c++) acc[r][c] += a[r] * b[c];
        }
        __syncthreads();
    }
    #pragma unroll
    for (int r = 0; r < 4; r++)
        #pragma unroll
        for (int c = 0; c < 4; c++)
            out[(rt + ty*4 + r)*E_ + ct + tx*4 + c] = acc[r][c] + bo[ct + tx*4 + c];
}

// -------- launch --------
extern "C" void kernel_launch(void* const* d_in, const int* in_sizes, int n_in,
                              void* d_out, int out_size) {
    const float* image = (const float*)d_in[0];
    const float* text  = (const float*)d_in[1];
    const void*  mask  =                d_in[2];
    const float* Wq    = (const float*)d_in[3];
    const float* Wk    = (const float*)d_in[4];
    const float* Wv    = (const float*)d_in[5];
    const float* Wo    = (const float*)d_in[6];
    const float* bo    = (const float*)d_in[7];
    float* out = (float*)d_out;

    const int SMEM_BYTES = (Q_*EST_ + K_*D_ + K_*D_ + Q_ + 4 + K_ + 256 + 256 + 32 + 32 + 32) * 4;
    cudaFuncSetAttribute(attn_kernel, cudaFuncAttributeMaxDynamicSharedMemorySize, SMEM_BYTES);

    mask_kernel<<<1, 256>>>(mask);

    float* d_q; cudaGetSymbolAddress((void**)&d_q, g_query);
    float* d_k; cudaGetSymbolAddress((void**)&d_k, g_key);
    float* d_v; cudaGetSymbolAddress((void**)&d_v, g_value);
    proj2_kernel<<<dim3((I_*Q_)/64, H_), 256>>>(image, Wq, d_q, 0);
    proj2_kernel<<<dim3((T_*K_)/64, H_), 256>>>(text,  Wk, d_k, 1);
    proj2_kernel<<<dim3((T_*K_)/64, H_), 256>>>(text,  Wv, d_v, 2);

    int wAttn = out_size >= (OUT_N + ATT_N);
    int wText = out_size >= (OUT_N + 2*ATT_N);
    attn_kernel<<<dim3(I_*H_, T_/TT_), 256, SMEM_BYTES>>>(out, wAttn, wText);

    if (out_size >= OUT_N)
        fc_kernel<<<dim3(16, 8), 256>>>(Wo, bo, out);
}